// round 15
// baseline (speedup 1.0000x reference)
#include <cuda_runtime.h>
#include <cuda_fp16.h>
#include <math.h>
#include <stdint.h>

#define D_RES  1024
#define NH     16
#define DH     64
#define DMLP   4096
#define SEQ    2048
#define BATCH  2
#define NTOK   (BATCH*SEQ)      /* 4096 */
#define N3     (3*D_RES)        /* 3072 */
#define EPSLN  1e-5f

/* ------------------------------------------------------------------ */
/* Scratch: __device__ globals                                         */
/* ------------------------------------------------------------------ */
__device__ __half g_Wqkv[D_RES * N3];                /* [1024][3072] k-major */
__device__ float  g_bias_qkv[N3];
__device__ __half g_WOh[D_RES * D_RES];              /* [1024][1024] natural */
__device__ __half g_Winh[D_RES * DMLP];              /* [1024][4096] natural */
__device__ __half g_Wouth[DMLP * D_RES];             /* [4096][1024] natural */
__device__ __half g_xln[(size_t)NTOK * D_RES];
__device__ __half g_qkv[(size_t)NTOK * N3];
__device__ __half g_z[(size_t)NTOK * D_RES];
__device__ float  g_resid_mid[(size_t)NTOK * D_RES];
__device__ __half g_y[(size_t)NTOK * D_RES];
__device__ __half g_post[(size_t)NTOK * DMLP];

/* ------------------------------------------------------------------ */
/* PTX helpers                                                         */
/* ------------------------------------------------------------------ */
__device__ __forceinline__ uint32_t smem_u32(const void* p) {
    uint32_t a;
    asm("{ .reg .u64 t; cvta.to.shared.u64 t, %1; cvt.u32.u64 %0, t; }" : "=r"(a) : "l"(p));
    return a;
}
/* .cg = L2-only staging; tile data is never re-read through L1 */
__device__ __forceinline__ void cp16(uint32_t dst, const void* src) {
    asm volatile("cp.async.cg.shared.global [%0], [%1], 16;" :: "r"(dst), "l"(src));
}
#define CP_COMMIT()  asm volatile("cp.async.commit_group;" ::: "memory")
#define CP_WAIT0()   asm volatile("cp.async.wait_group 0;" ::: "memory")

__device__ __forceinline__ void ldsm4(uint32_t a, uint32_t& r0, uint32_t& r1,
                                      uint32_t& r2, uint32_t& r3) {
    asm volatile("ldmatrix.sync.aligned.m8n8.x4.shared.b16 {%0,%1,%2,%3}, [%4];"
                 : "=r"(r0), "=r"(r1), "=r"(r2), "=r"(r3) : "r"(a));
}
__device__ __forceinline__ void ldsm4t(uint32_t a, uint32_t& r0, uint32_t& r1,
                                       uint32_t& r2, uint32_t& r3) {
    asm volatile("ldmatrix.sync.aligned.m8n8.x4.trans.shared.b16 {%0,%1,%2,%3}, [%4];"
                 : "=r"(r0), "=r"(r1), "=r"(r2), "=r"(r3) : "r"(a));
}
__device__ __forceinline__ void mma_f16(float* c, const uint32_t* a,
                                        uint32_t b0, uint32_t b1) {
    asm volatile("mma.sync.aligned.m16n8k16.row.col.f32.f16.f16.f32 "
                 "{%0,%1,%2,%3}, {%4,%5,%6,%7}, {%8,%9}, {%0,%1,%2,%3};"
                 : "+f"(c[0]), "+f"(c[1]), "+f"(c[2]), "+f"(c[3])
                 : "r"(a[0]), "r"(a[1]), "r"(a[2]), "r"(a[3]), "r"(b0), "r"(b1));
}

/* ------------------------------------------------------------------ */
/* Layouts:                                                            */
/*   A tiles / K / V tiles: ROWS x 64 halves, stride 72 (144 B)        */
/*   dense B tiles: 64 k-rows x 128 n halves, stride 136 (272 B)       */
/* ------------------------------------------------------------------ */
#define STRH 72
#define STRB 136
#define TILE_A_B (128 * STRH * 2)      /* 18432 B */
#define TILE_B_B (64 * STRB * 2)       /* 17408 B */
#define TK_B     (64 * STRH * 2)       /* 9216 B (flash K/V tile) */

/* A-style tile: ROWS x 64 halves, stride 72 */
template <int ROWS, int NT>
__device__ __forceinline__ void stage_tile_h(uint32_t s, const __half* __restrict__ g,
                                             int ld, int k0) {
    #pragma unroll
    for (int i = 0; i < (ROWS * 8) / NT; i++) {
        int u = threadIdx.x + i * NT;
        int r = u >> 3, c = u & 7;
        cp16(s + (uint32_t)((r * STRH + c * 8) * 2), g + (size_t)r * ld + k0 + c * 8);
    }
}

/* dense k-major B tile: 64 k-rows x 128 n halves, stride 136.          */
__device__ __forceinline__ void stage_tile_b(uint32_t s, const __half* __restrict__ g,
                                             int ld, int k0) {
    #pragma unroll
    for (int i = 0; i < 4; i++) {
        int u = threadIdx.x + i * 256;
        int r = u >> 4, c = u & 15;
        cp16(s + (uint32_t)((r * STRB + c * 8) * 2),
             g + (size_t)(k0 + r) * ld + c * 8);
    }
}

/* ---------------- MMA chunk, k-major B (trans ldmatrix) ------------ */
template <int MT, int NT, int WN, int BSTR>
__device__ __forceinline__ void compute_chunk_bt(uint32_t a_s, uint32_t b_s,
                                                 float (&acc)[MT][NT][4]) {
    int lane = threadIdx.x & 31, wid = threadIdx.x >> 5;
    int wm = wid / WN, wn = wid % WN;
    uint32_t ab = a_s + (uint32_t)(((wm * (MT * 16) + (lane & 15)) * STRH
                                    + ((lane >> 4) << 3)) * 2);
    uint32_t bb = b_s + (uint32_t)(((lane & 15) * BSTR
                                    + wn * (NT * 8) + ((lane >> 4) << 3)) * 2);
    #pragma unroll
    for (int ks = 0; ks < 4; ks++) {
        uint32_t af[MT][4], bf[NT][2];
        #pragma unroll
        for (int mt = 0; mt < MT; mt++)
            ldsm4(ab + mt * (16 * STRH * 2) + ks * 32,
                  af[mt][0], af[mt][1], af[mt][2], af[mt][3]);
        #pragma unroll
        for (int p = 0; p < NT / 2; p++) {
            uint32_t r0, r1, r2, r3;
            ldsm4t(bb + (uint32_t)((ks * 16 * BSTR + p * 16) * 2), r0, r1, r2, r3);
            bf[2 * p][0] = r0; bf[2 * p][1] = r1;
            bf[2 * p + 1][0] = r2; bf[2 * p + 1][1] = r3;
        }
        #pragma unroll
        for (int mt = 0; mt < MT; mt++)
            #pragma unroll
            for (int nt = 0; nt < NT; nt++)
                mma_f16(acc[mt][nt], af[mt], bf[nt][0], bf[nt][1]);
    }
}

/* ------------------------------------------------------------------ */
/* Dense GEMM: double-buffer, K-chunk 64, SINGLE barrier per chunk     */
/* smem = 2 * (18432 + 17408) = 71680 B -> 2 CTAs/SM                   */
/* ------------------------------------------------------------------ */
#define STAGE_B (TILE_A_B + TILE_B_B)
#define SMEM_DENSE (2 * STAGE_B)

__device__ __forceinline__ void mma_run_dense(uint32_t sb,
        const __half* __restrict__ A, int lda,
        const __half* __restrict__ Bn, int ldb, int nc, float (&acc)[4][4][4]) {
    uint32_t aS[2] = { sb, sb + STAGE_B };
    uint32_t bS[2] = { sb + TILE_A_B, sb + STAGE_B + TILE_A_B };

    stage_tile_h<128, 256>(aS[0], A, lda, 0);
    stage_tile_b(bS[0], Bn, ldb, 0);
    CP_COMMIT();

    for (int c = 0; c < nc; c++) {
        CP_WAIT0();
        __syncthreads();
        if (c + 1 < nc) {
            int nb = (c + 1) & 1;
            stage_tile_h<128, 256>(aS[nb], A, lda, (c + 1) * 64);
            stage_tile_b(bS[nb], Bn, ldb, (c + 1) * 64);
            CP_COMMIT();
        }
        compute_chunk_bt<4, 4, 4, STRB>(aS[c & 1], bS[c & 1], acc);
    }
}

__device__ __forceinline__ float gelu_exact(float x) {
    return 0.5f * x * (1.f + erff(x * 0.70710678118654752f));
}

enum { EPI_BIAS = 1, EPI_BIAS_RES = 2, EPI_BIAS_GELU = 3 };

template <int EPI, bool HOUT>
__device__ __forceinline__ void epilogue_dense_h(float (&acc)[4][4][4],
        void* __restrict__ Cv, int ldc, int bm, int bn,
        const float* __restrict__ bias, const float* __restrict__ res, int ldres) {
    int lane = threadIdx.x & 31, wid = threadIdx.x >> 5;
    int wm = wid >> 2, wn = wid & 3;
    int r0 = bm + wm * 64 + (lane >> 2);
    int c0 = bn + wn * 32 + 2 * (lane & 3);
    #pragma unroll
    for (int mt = 0; mt < 4; mt++) {
        #pragma unroll
        for (int nt = 0; nt < 4; nt++) {
            int col = c0 + nt * 8;
            float2 bb = *(const float2*)(bias + col);
            #pragma unroll
            for (int h = 0; h < 2; h++) {
                int row = r0 + mt * 16 + h * 8;
                float v0 = acc[mt][nt][2 * h] + bb.x;
                float v1 = acc[mt][nt][2 * h + 1] + bb.y;
                if (EPI == EPI_BIAS_RES) {
                    float2 rr = *(const float2*)(res + (size_t)row * ldres + col);
                    v0 += rr.x; v1 += rr.y;
                }
                if (EPI == EPI_BIAS_GELU) { v0 = gelu_exact(v0); v1 = gelu_exact(v1); }
                if (HOUT) {
                    *(__half2*)((__half*)Cv + (size_t)row * ldc + col) =
                        __floats2half2_rn(v0, v1);
                } else {
                    *(float2*)((float*)Cv + (size_t)row * ldc + col) =
                        make_float2(v0, v1);
                }
            }
        }
    }
}

template <int EPI, bool HOUT>
__global__ void __launch_bounds__(256, 2) h_gemm_k(const __half* __restrict__ A, int lda,
        const __half* __restrict__ Bn, int ldb, void* __restrict__ C, int ldc, int K,
        const float* __restrict__ bias, const float* __restrict__ res, int ldres) {
    extern __shared__ __half smh[];
    uint32_t sb = smem_u32(smh);
    int bm = blockIdx.y * 128, bn = blockIdx.x * 128;
    float acc[4][4][4] = {};
    mma_run_dense(sb, A + (size_t)bm * lda, lda, Bn + bn, ldb, K / 64, acc);
    epilogue_dense_h<EPI, HOUT>(acc, C, ldc, bm, bn, bias, res, ldres);
}

/* ------------------------------------------------------------------ */
/* Flash attention, FA2 layout (R13 structure)                         */
/* ------------------------------------------------------------------ */
#define FLASH_SMEM (TILE_A_B + 4 * TK_B)

__global__ void __launch_bounds__(256, 2) flash_k(const __half* __restrict__ qkv,
                                                  __half* __restrict__ Z) {
    extern __shared__ __half smh[];
    uint32_t sb = smem_u32(smh);
    const uint32_t sQ  = sb;
    const uint32_t sK0 = sb + TILE_A_B;
    const uint32_t sV0 = sb + TILE_A_B + 2 * TK_B;

    int bh = blockIdx.y, b = bh >> 4, h = bh & 15;
    int lane = threadIdx.x & 31, w = threadIdx.x >> 5;

    const __half* qbase = qkv + (size_t)b * SEQ * N3 + h * DH;
    const __half* kbase = qbase + D_RES;
    const __half* vbase = qbase + 2 * D_RES;
    __half* Zb = Z + (size_t)b * SEQ * D_RES + h * DH;

    const uint32_t ab0 = (uint32_t)(((w * 16 + (lane & 15)) * STRH
                                     + ((lane >> 4) << 3)) * 2);

    #pragma unroll 1
    for (int hf = 0; hf < 2; hf++) {
        int qt = hf ? (15 - (int)blockIdx.x) : (int)blockIdx.x;
        if (hf) __syncthreads();   /* previous half's smem reads done */

        stage_tile_h<128, 256>(sQ, qbase + (size_t)qt * 128 * N3, N3, 0);
        stage_tile_h<64, 256>(sK0, kbase, N3, 0);
        stage_tile_h<64, 256>(sV0, vbase, N3, 0);
        CP_COMMIT();

        int nkt = 2 * qt + 2;
        float m_i[2] = { -1e30f, -1e30f }, l_i[2] = { 0.f, 0.f };
        float oacc[8][4] = {};

        #pragma unroll 1
        for (int kt2 = 0; kt2 < nkt; kt2++) {
            CP_WAIT0();
            __syncthreads();
            uint32_t sK = sK0 + (uint32_t)(kt2 & 1) * TK_B;
            uint32_t sV = sV0 + (uint32_t)(kt2 & 1) * TK_B;
            if (kt2 + 1 < nkt) {
                uint32_t alt = (uint32_t)((kt2 + 1) & 1) * TK_B;
                stage_tile_h<64, 256>(sK0 + alt, kbase + (size_t)(kt2 + 1) * 64 * N3, N3, 0);
                stage_tile_h<64, 256>(sV0 + alt, vbase + (size_t)(kt2 + 1) * 64 * N3, N3, 0);
                CP_COMMIT();
            }

            /* ---- S = Q K^T ---- */
            float sacc[8][4] = {};
            {
                uint32_t ab = sQ + ab0;
                uint32_t bb = sK + (uint32_t)((((lane & 15)) * STRH
                                               + ((lane >> 4) << 3)) * 2);
                #pragma unroll
                for (int ks = 0; ks < 4; ks++) {
                    uint32_t af[4];
                    ldsm4(ab + ks * 32, af[0], af[1], af[2], af[3]);
                    uint32_t bf[8][2];
                    #pragma unroll
                    for (int p = 0; p < 4; p++) {
                        uint32_t r0, r1, r2, r3;
                        ldsm4(bb + p * (16 * STRH * 2) + ks * 32, r0, r1, r2, r3);
                        bf[2 * p][0] = r0; bf[2 * p][1] = r2;
                        bf[2 * p + 1][0] = r1; bf[2 * p + 1][1] = r3;
                    }
                    #pragma unroll
                    for (int nt = 0; nt < 8; nt++)
                        mma_f16(sacc[nt], af, bf[nt][0], bf[nt][1]);
                }
            }

            /* ---- scale + causal mask ---- */
            int rg = qt * 128 + w * 16 + (lane >> 2);
            int cg0 = kt2 * 64 + 2 * (lane & 3);
            bool diag = (kt2 >= 2 * qt);
            #pragma unroll
            for (int nt = 0; nt < 8; nt++)
                #pragma unroll
                for (int hh = 0; hh < 2; hh++) {
                    int r = rg + 8 * hh;
                    int c = cg0 + nt * 8;
                    float v0 = sacc[nt][2 * hh] * 0.125f;
                    float v1 = sacc[nt][2 * hh + 1] * 0.125f;
                    if (diag) {
                        if (c > r)     v0 = -1e30f;
                        if (c + 1 > r) v1 = -1e30f;
                    }
                    sacc[nt][2 * hh] = v0;
                    sacc[nt][2 * hh + 1] = v1;
                }

            /* ---- row max (quad shfl only) ---- */
            float m_new[2], alpha[2];
            #pragma unroll
            for (int hh = 0; hh < 2; hh++) {
                float v = -1e30f;
                #pragma unroll
                for (int nt = 0; nt < 8; nt++) {
                    v = fmaxf(v, sacc[nt][2 * hh]);
                    v = fmaxf(v, sacc[nt][2 * hh + 1]);
                }
                v = fmaxf(v, __shfl_xor_sync(0xffffffffu, v, 1));
                v = fmaxf(v, __shfl_xor_sync(0xffffffffu, v, 2));
                m_new[hh] = fmaxf(m_i[hh], v);
                alpha[hh] = __expf(m_i[hh] - m_new[hh]);
                m_i[hh] = m_new[hh];
            }

            /* ---- P = exp(S - m) in registers ---- */
            uint32_t ph[8][2];
            float rs[2] = { 0.f, 0.f };
            #pragma unroll
            for (int nt = 0; nt < 8; nt++)
                #pragma unroll
                for (int hh = 0; hh < 2; hh++) {
                    float p0 = __expf(sacc[nt][2 * hh] - m_new[hh]);
                    float p1 = __expf(sacc[nt][2 * hh + 1] - m_new[hh]);
                    rs[hh] += p0 + p1;
                    __half2 hp = __floats2half2_rn(p0, p1);
                    ph[nt][hh] = *(uint32_t*)&hp;
                }
            #pragma unroll
            for (int hh = 0; hh < 2; hh++) {
                float s2 = rs[hh];
                s2 += __shfl_xor_sync(0xffffffffu, s2, 1);
                s2 += __shfl_xor_sync(0xffffffffu, s2, 2);
                l_i[hh] = l_i[hh] * alpha[hh] + s2;
                #pragma unroll
                for (int nt = 0; nt < 8; nt++) {
                    oacc[nt][2 * hh]     *= alpha[hh];
                    oacc[nt][2 * hh + 1] *= alpha[hh];
                }
            }

            /* ---- O += P V ---- */
            {
                uint32_t vb = sV + (uint32_t)(((lane & 15) * STRH
                                               + ((lane >> 4) << 3)) * 2);
                #pragma unroll
                for (int ks = 0; ks < 4; ks++) {
                    uint32_t af[4] = { ph[2 * ks][0], ph[2 * ks][1],
                                       ph[2 * ks + 1][0], ph[2 * ks + 1][1] };
                    uint32_t vf[8][2];
                    #pragma unroll
                    for (int p = 0; p < 4; p++) {
                        uint32_t r0, r1, r2, r3;
                        ldsm4t(vb + (uint32_t)((ks * 16 * STRH + p * 16) * 2),
                               r0, r1, r2, r3);
                        vf[2 * p][0] = r0; vf[2 * p][1] = r1;
                        vf[2 * p + 1][0] = r2; vf[2 * p + 1][1] = r3;
                    }
                    #pragma unroll
                    for (int nt = 0; nt < 8; nt++)
                        mma_f16(oacc[nt], af, vf[nt][0], vf[nt][1]);
                }
            }
        }

        /* ---- Z = O / l ---- */
        #pragma unroll
        for (int hh = 0; hh < 2; hh++) {
            float inv = 1.f / l_i[hh];
            int row = qt * 128 + w * 16 + (lane >> 2) + 8 * hh;
            #pragma unroll
            for (int nt = 0; nt < 8; nt++) {
                int col = nt * 8 + 2 * (lane & 3);
                *(__half2*)(Zb + (size_t)row * D_RES + col) =
                    __floats2half2_rn(oacc[nt][2 * hh] * inv,
                                      oacc[nt][2 * hh + 1] * inv);
            }
        }
    }
}

/* ------------------------------------------------------------------ */
/* LayerNorm: fp32 in -> half out (single pass)                        */
/* ------------------------------------------------------------------ */
__global__ void __launch_bounds__(256) layernorm_h_k(const float* __restrict__ in,
        const float* __restrict__ w, const float* __restrict__ b,
        __half* __restrict__ out) {
    int row = blockIdx.x, t = threadIdx.x;
    const float* x = in + (size_t)row * D_RES;
    float4 v = *(const float4*)(x + t * 4);
    float s = v.x + v.y + v.z + v.w;
    float q = v.x * v.x + v.y * v.y + v.z * v.z + v.w * v.w;
    #pragma unroll
    for (int o = 16; o > 0; o >>= 1) {
        s += __shfl_xor_sync(0xffffffffu, s, o);
        q += __shfl_xor_sync(0xffffffffu, q, o);
    }
    __shared__ float rs[8], rq[8];
    int wid = t >> 5;
    if ((t & 31) == 0) { rs[wid] = s; rq[wid] = q; }
    __syncthreads();
    s = rs[0] + rs[1] + rs[2] + rs[3] + rs[4] + rs[5] + rs[6] + rs[7];
    q = rq[0] + rq[1] + rq[2] + rq[3] + rq[4] + rq[5] + rq[6] + rq[7];
    float mean = s * (1.f / D_RES);
    float inv = rsqrtf(q * (1.f / D_RES) - mean * mean + EPSLN);
    float4 wv = *(const float4*)(w + t * 4);
    float4 bv = *(const float4*)(b + t * 4);
    __half* orow = out + (size_t)row * D_RES + t * 4;
    *(__half2*)(orow)     = __floats2half2_rn((v.x - mean) * inv * wv.x + bv.x,
                                              (v.y - mean) * inv * wv.y + bv.y);
    *(__half2*)(orow + 2) = __floats2half2_rn((v.z - mean) * inv * wv.z + bv.z,
                                              (v.w - mean) * inv * wv.w + bv.w);
}

/* ------------------------------------------------------------------ */
/* Weight prep                                                         */
/* ------------------------------------------------------------------ */
__global__ void pack_qkv_k(const float* __restrict__ WQ, const float* __restrict__ WK,
                           const float* __restrict__ WV, const float* __restrict__ bQ,
                           const float* __restrict__ bK, const float* __restrict__ bV) {
    int idx = blockIdx.x * blockDim.x + threadIdx.x;
    if (idx < D_RES * N3) {
        int d = idx / N3;
        int n = idx % N3;
        int sel = n / D_RES;
        int c = n % D_RES;
        int h = c / DH, e = c % DH;
        const float* W = (sel == 0) ? WQ : (sel == 1) ? WK : WV;
        g_Wqkv[idx] = __float2half_rn(W[((size_t)h * D_RES + d) * DH + e]);
    }
    if (idx < N3) {
        const float* bb = (idx < D_RES) ? bQ : (idx < 2 * D_RES) ? bK : bV;
        g_bias_qkv[idx] = bb[idx % D_RES];
    }
}

/* one kernel converting all three weight matrices fp32 -> fp16 */
#define CVT_N0 (D_RES * D_RES / 8)             /* WO   */
#define CVT_N1 (CVT_N0 + D_RES * DMLP / 8)     /* +Win */
#define CVT_N2 (CVT_N1 + DMLP * D_RES / 8)     /* +Wout*/
__global__ void __launch_bounds__(256) cvt_all_k(const float* __restrict__ WO,
        const float* __restrict__ Win, const float* __restrict__ Wout,
        __half* __restrict__ dWO, __half* __restrict__ dWin,
        __half* __restrict__ dWout) {
    int i = blockIdx.x * blockDim.x + threadIdx.x;
    if (i >= CVT_N2) return;
    const float* src;
    __half* dst;
    int j;
    if (i < CVT_N0)      { src = WO;   dst = dWO;   j = i; }
    else if (i < CVT_N1) { src = Win;  dst = dWin;  j = i - CVT_N0; }
    else                 { src = Wout; dst = dWout; j = i - CVT_N1; }
    float4 a = *(const float4*)(src + (size_t)j * 8);
    float4 b = *(const float4*)(src + (size_t)j * 8 + 4);
    __half2 h0 = __floats2half2_rn(a.x, a.y);
    __half2 h1 = __floats2half2_rn(a.z, a.w);
    __half2 h2 = __floats2half2_rn(b.x, b.y);
    __half2 h3 = __floats2half2_rn(b.z, b.w);
    uint4 o;
    o.x = *(uint32_t*)&h0; o.y = *(uint32_t*)&h1;
    o.z = *(uint32_t*)&h2; o.w = *(uint32_t*)&h3;
    *(uint4*)(dst + (size_t)j * 8) = o;
}

/* ------------------------------------------------------------------ */
/* Launch                                                              */
/* ------------------------------------------------------------------ */
extern "C" void kernel_launch(void* const* d_in, const int* in_sizes, int n_in,
                              void* d_out, int out_size) {
    const float* resid_pre = (const float*)d_in[0];
    const float* ln1_w = (const float*)d_in[1];
    const float* ln1_b = (const float*)d_in[2];
    const float* WQ = (const float*)d_in[3];
    const float* bQ = (const float*)d_in[4];
    const float* WK = (const float*)d_in[5];
    const float* bK = (const float*)d_in[6];
    const float* WV = (const float*)d_in[7];
    const float* bV = (const float*)d_in[8];
    const float* WO = (const float*)d_in[9];
    const float* bO = (const float*)d_in[10];
    const float* ln2_w = (const float*)d_in[11];
    const float* ln2_b = (const float*)d_in[12];
    const float* Win  = (const float*)d_in[13];
    const float* bin  = (const float*)d_in[14];
    const float* Wout = (const float*)d_in[15];
    const float* bout = (const float*)d_in[16];
    float* out = (float*)d_out;

    __half *p_Wqkv, *p_WOh, *p_Winh, *p_Wouth, *p_xln, *p_qkv, *p_z, *p_y, *p_post;
    float *p_bias, *p_mid;
    cudaGetSymbolAddress((void**)&p_Wqkv, g_Wqkv);
    cudaGetSymbolAddress((void**)&p_bias, g_bias_qkv);
    cudaGetSymbolAddress((void**)&p_WOh, g_WOh);
    cudaGetSymbolAddress((void**)&p_Winh, g_Winh);
    cudaGetSymbolAddress((void**)&p_Wouth, g_Wouth);
    cudaGetSymbolAddress((void**)&p_xln, g_xln);
    cudaGetSymbolAddress((void**)&p_qkv, g_qkv);
    cudaGetSymbolAddress((void**)&p_z, g_z);
    cudaGetSymbolAddress((void**)&p_mid, g_resid_mid);
    cudaGetSymbolAddress((void**)&p_y, g_y);
    cudaGetSymbolAddress((void**)&p_post, g_post);

    cudaFuncSetAttribute(h_gemm_k<EPI_BIAS, true>,
                         cudaFuncAttributeMaxDynamicSharedMemorySize, SMEM_DENSE);
    cudaFuncSetAttribute(h_gemm_k<EPI_BIAS_RES, false>,
                         cudaFuncAttributeMaxDynamicSharedMemorySize, SMEM_DENSE);
    cudaFuncSetAttribute(h_gemm_k<EPI_BIAS_GELU, true>,
                         cudaFuncAttributeMaxDynamicSharedMemorySize, SMEM_DENSE);
    cudaFuncSetAttribute(flash_k,
                         cudaFuncAttributeMaxDynamicSharedMemorySize, FLASH_SMEM);

    /* weight prep */
    pack_qkv_k<<<(D_RES * N3 + 255) / 256, 256>>>(WQ, WK, WV, bQ, bK, bV);
    cvt_all_k<<<(CVT_N2 + 255) / 256, 256>>>(WO, Win, Wout, p_WOh, p_Winh, p_Wouth);

    /* LN1 (fp32 -> half) */
    layernorm_h_k<<<NTOK, 256>>>(resid_pre, ln1_w, ln1_b, p_xln);

    /* QKV = xln @ Wqkv + bias -> half */
    h_gemm_k<EPI_BIAS, true><<<dim3(N3 / 128, NTOK / 128), 256, SMEM_DENSE>>>(
        p_xln, D_RES, p_Wqkv, N3, p_qkv, N3, D_RES, p_bias, nullptr, 0);

    /* fused attention (FA2 layout, V consumed in-place) */
    flash_k<<<dim3(8, BATCH * NH), 256, FLASH_SMEM>>>(p_qkv, p_z);

    /* resid_mid = Z @ W_O + b_O + resid_pre -> fp32 */
    h_gemm_k<EPI_BIAS_RES, false><<<dim3(D_RES / 128, NTOK / 128), 256, SMEM_DENSE>>>(
        p_z, D_RES, p_WOh, D_RES, p_mid, D_RES, D_RES, bO, resid_pre, D_RES);

    /* LN2 (fp32 -> half) */
    layernorm_h_k<<<NTOK, 256>>>(p_mid, ln2_w, ln2_b, p_y);

    /* post = gelu(y @ W_in + b_in) -> half */
    h_gemm_k<EPI_BIAS_GELU, true><<<dim3(DMLP / 128, NTOK / 128), 256, SMEM_DENSE>>>(
        p_y, D_RES, p_Winh, DMLP, p_post, DMLP, D_RES, bin, nullptr, 0);

    /* out = post @ W_out + b_out + resid_mid -> fp32 */
    h_gemm_k<EPI_BIAS_RES, false><<<dim3(D_RES / 128, NTOK / 128), 256, SMEM_DENSE>>>(
        p_post, DMLP, p_Wouth, D_RES, out, D_RES, DMLP, bout, p_mid, D_RES);
}

// round 16
// speedup vs baseline: 1.0440x; 1.0440x over previous
#include <cuda_runtime.h>
#include <cuda_fp16.h>
#include <math.h>
#include <stdint.h>

#define D_RES  1024
#define NH     16
#define DH     64
#define DMLP   4096
#define SEQ    2048
#define BATCH  2
#define NTOK   (BATCH*SEQ)      /* 4096 */
#define N3     (3*D_RES)        /* 3072 */
#define EPSLN  1e-5f

/* ------------------------------------------------------------------ */
/* Scratch: __device__ globals                                         */
/* ------------------------------------------------------------------ */
__device__ __half g_Wqkv[D_RES * N3];                /* [1024][3072] k-major */
__device__ float  g_bias_qkv[N3];
__device__ __half g_WOh[D_RES * D_RES];              /* [1024][1024] natural */
__device__ __half g_Winh[D_RES * DMLP];              /* [1024][4096] natural */
__device__ __half g_Wouth[DMLP * D_RES];             /* [4096][1024] natural */
__device__ __half g_xln[(size_t)NTOK * D_RES];
__device__ __half g_qkv[(size_t)NTOK * N3];
__device__ __half g_z[(size_t)NTOK * D_RES];
__device__ float  g_resid_mid[(size_t)NTOK * D_RES];
__device__ __half g_y[(size_t)NTOK * D_RES];
__device__ __half g_post[(size_t)NTOK * DMLP];

/* ------------------------------------------------------------------ */
/* PTX helpers                                                         */
/* ------------------------------------------------------------------ */
__device__ __forceinline__ uint32_t smem_u32(const void* p) {
    uint32_t a;
    asm("{ .reg .u64 t; cvta.to.shared.u64 t, %1; cvt.u32.u64 %0, t; }" : "=r"(a) : "l"(p));
    return a;
}
/* .ca: L1 allocation gives cross-CTA reuse on same SM (R15 lesson) */
__device__ __forceinline__ void cp16(uint32_t dst, const void* src) {
    asm volatile("cp.async.ca.shared.global [%0], [%1], 16;" :: "r"(dst), "l"(src));
}
#define CP_COMMIT()  asm volatile("cp.async.commit_group;" ::: "memory")
#define CP_WAIT0()   asm volatile("cp.async.wait_group 0;" ::: "memory")

__device__ __forceinline__ void ldsm4(uint32_t a, uint32_t& r0, uint32_t& r1,
                                      uint32_t& r2, uint32_t& r3) {
    asm volatile("ldmatrix.sync.aligned.m8n8.x4.shared.b16 {%0,%1,%2,%3}, [%4];"
                 : "=r"(r0), "=r"(r1), "=r"(r2), "=r"(r3) : "r"(a));
}
__device__ __forceinline__ void ldsm4t(uint32_t a, uint32_t& r0, uint32_t& r1,
                                       uint32_t& r2, uint32_t& r3) {
    asm volatile("ldmatrix.sync.aligned.m8n8.x4.trans.shared.b16 {%0,%1,%2,%3}, [%4];"
                 : "=r"(r0), "=r"(r1), "=r"(r2), "=r"(r3) : "r"(a));
}
__device__ __forceinline__ void mma_f16(float* c, const uint32_t* a,
                                        uint32_t b0, uint32_t b1) {
    asm volatile("mma.sync.aligned.m16n8k16.row.col.f32.f16.f16.f32 "
                 "{%0,%1,%2,%3}, {%4,%5,%6,%7}, {%8,%9}, {%0,%1,%2,%3};"
                 : "+f"(c[0]), "+f"(c[1]), "+f"(c[2]), "+f"(c[3])
                 : "r"(a[0]), "r"(a[1]), "r"(a[2]), "r"(a[3]), "r"(b0), "r"(b1));
}

/* ------------------------------------------------------------------ */
/* Layouts:                                                            */
/*   A tiles / K / V tiles: ROWS x 64 halves, stride 72 (144 B)        */
/*   dense B tiles: 64 k-rows x 128 n halves, stride 136 (272 B)       */
/* ------------------------------------------------------------------ */
#define STRH 72
#define STRB 136
#define TILE_A_B (128 * STRH * 2)      /* 18432 B */
#define TILE_B_B (64 * STRB * 2)       /* 17408 B */
#define TK_B     (64 * STRH * 2)       /* 9216 B (flash K/V tile) */

/* A-style tile: ROWS x 64 halves, stride 72 */
template <int ROWS, int NT>
__device__ __forceinline__ void stage_tile_h(uint32_t s, const __half* __restrict__ g,
                                             int ld, int k0) {
    #pragma unroll
    for (int i = 0; i < (ROWS * 8) / NT; i++) {
        int u = threadIdx.x + i * NT;
        int r = u >> 3, c = u & 7;
        cp16(s + (uint32_t)((r * STRH + c * 8) * 2), g + (size_t)r * ld + k0 + c * 8);
    }
}

/* dense k-major B tile: 64 k-rows x 128 n halves, stride 136.          */
__device__ __forceinline__ void stage_tile_b(uint32_t s, const __half* __restrict__ g,
                                             int ld, int k0) {
    #pragma unroll
    for (int i = 0; i < 4; i++) {
        int u = threadIdx.x + i * 256;
        int r = u >> 4, c = u & 15;
        cp16(s + (uint32_t)((r * STRB + c * 8) * 2),
             g + (size_t)(k0 + r) * ld + c * 8);
    }
}

/* ---------------- MMA chunk, k-major B (trans ldmatrix) ------------ */
template <int MT, int NT, int WN, int BSTR>
__device__ __forceinline__ void compute_chunk_bt(uint32_t a_s, uint32_t b_s,
                                                 float (&acc)[MT][NT][4]) {
    int lane = threadIdx.x & 31, wid = threadIdx.x >> 5;
    int wm = wid / WN, wn = wid % WN;
    uint32_t ab = a_s + (uint32_t)(((wm * (MT * 16) + (lane & 15)) * STRH
                                    + ((lane >> 4) << 3)) * 2);
    uint32_t bb = b_s + (uint32_t)(((lane & 15) * BSTR
                                    + wn * (NT * 8) + ((lane >> 4) << 3)) * 2);
    #pragma unroll
    for (int ks = 0; ks < 4; ks++) {
        uint32_t af[MT][4], bf[NT][2];
        #pragma unroll
        for (int mt = 0; mt < MT; mt++)
            ldsm4(ab + mt * (16 * STRH * 2) + ks * 32,
                  af[mt][0], af[mt][1], af[mt][2], af[mt][3]);
        #pragma unroll
        for (int p = 0; p < NT / 2; p++) {
            uint32_t r0, r1, r2, r3;
            ldsm4t(bb + (uint32_t)((ks * 16 * BSTR + p * 16) * 2), r0, r1, r2, r3);
            bf[2 * p][0] = r0; bf[2 * p][1] = r1;
            bf[2 * p + 1][0] = r2; bf[2 * p + 1][1] = r3;
        }
        #pragma unroll
        for (int mt = 0; mt < MT; mt++)
            #pragma unroll
            for (int nt = 0; nt < NT; nt++)
                mma_f16(acc[mt][nt], af[mt], bf[nt][0], bf[nt][1]);
    }
}

/* ------------------------------------------------------------------ */
/* Dense GEMM: double-buffer, K-chunk 64, SINGLE barrier per chunk     */
/* smem = 2 * (18432 + 17408) = 71680 B -> 2 CTAs/SM                   */
/* ------------------------------------------------------------------ */
#define STAGE_B (TILE_A_B + TILE_B_B)
#define SMEM_DENSE (2 * STAGE_B)

__device__ __forceinline__ void mma_run_dense(uint32_t sb,
        const __half* __restrict__ A, int lda,
        const __half* __restrict__ Bn, int ldb, int nc, float (&acc)[4][4][4]) {
    uint32_t aS[2] = { sb, sb + STAGE_B };
    uint32_t bS[2] = { sb + TILE_A_B, sb + STAGE_B + TILE_A_B };

    stage_tile_h<128, 256>(aS[0], A, lda, 0);
    stage_tile_b(bS[0], Bn, ldb, 0);
    CP_COMMIT();

    for (int c = 0; c < nc; c++) {
        CP_WAIT0();
        __syncthreads();
        if (c + 1 < nc) {
            int nb = (c + 1) & 1;
            stage_tile_h<128, 256>(aS[nb], A, lda, (c + 1) * 64);
            stage_tile_b(bS[nb], Bn, ldb, (c + 1) * 64);
            CP_COMMIT();
        }
        compute_chunk_bt<4, 4, 4, STRB>(aS[c & 1], bS[c & 1], acc);
    }
}

__device__ __forceinline__ float gelu_exact(float x) {
    return 0.5f * x * (1.f + erff(x * 0.70710678118654752f));
}

enum { EPI_BIAS = 1, EPI_BIAS_RES = 2, EPI_BIAS_GELU = 3 };

template <int EPI, bool HOUT>
__device__ __forceinline__ void epilogue_dense_h(float (&acc)[4][4][4],
        void* __restrict__ Cv, int ldc, int bm, int bn,
        const float* __restrict__ bias, const float* __restrict__ res, int ldres) {
    int lane = threadIdx.x & 31, wid = threadIdx.x >> 5;
    int wm = wid >> 2, wn = wid & 3;
    int r0 = bm + wm * 64 + (lane >> 2);
    int c0 = bn + wn * 32 + 2 * (lane & 3);
    #pragma unroll
    for (int mt = 0; mt < 4; mt++) {
        #pragma unroll
        for (int nt = 0; nt < 4; nt++) {
            int col = c0 + nt * 8;
            float2 bb = *(const float2*)(bias + col);
            #pragma unroll
            for (int h = 0; h < 2; h++) {
                int row = r0 + mt * 16 + h * 8;
                float v0 = acc[mt][nt][2 * h] + bb.x;
                float v1 = acc[mt][nt][2 * h + 1] + bb.y;
                if (EPI == EPI_BIAS_RES) {
                    float2 rr = *(const float2*)(res + (size_t)row * ldres + col);
                    v0 += rr.x; v1 += rr.y;
                }
                if (EPI == EPI_BIAS_GELU) { v0 = gelu_exact(v0); v1 = gelu_exact(v1); }
                if (HOUT) {
                    *(__half2*)((__half*)Cv + (size_t)row * ldc + col) =
                        __floats2half2_rn(v0, v1);
                } else {
                    *(float2*)((float*)Cv + (size_t)row * ldc + col) =
                        make_float2(v0, v1);
                }
            }
        }
    }
}

template <int EPI, bool HOUT>
__global__ void __launch_bounds__(256, 2) h_gemm_k(const __half* __restrict__ A, int lda,
        const __half* __restrict__ Bn, int ldb, void* __restrict__ C, int ldc, int K,
        const float* __restrict__ bias, const float* __restrict__ res, int ldres) {
    extern __shared__ __half smh[];
    uint32_t sb = smem_u32(smh);
    int bm = blockIdx.y * 128, bn = blockIdx.x * 128;
    float acc[4][4][4] = {};
    mma_run_dense(sb, A + (size_t)bm * lda, lda, Bn + bn, ldb, K / 64, acc);
    epilogue_dense_h<EPI, HOUT>(acc, C, ldc, bm, bn, bias, res, ldres);
}

/* ------------------------------------------------------------------ */
/* Flash attention, FA2 layout (R13 structure)                         */
/* ------------------------------------------------------------------ */
#define FLASH_SMEM (TILE_A_B + 4 * TK_B)

__global__ void __launch_bounds__(256, 2) flash_k(const __half* __restrict__ qkv,
                                                  __half* __restrict__ Z) {
    extern __shared__ __half smh[];
    uint32_t sb = smem_u32(smh);
    const uint32_t sQ  = sb;
    const uint32_t sK0 = sb + TILE_A_B;
    const uint32_t sV0 = sb + TILE_A_B + 2 * TK_B;

    int bh = blockIdx.y, b = bh >> 4, h = bh & 15;
    int lane = threadIdx.x & 31, w = threadIdx.x >> 5;

    const __half* qbase = qkv + (size_t)b * SEQ * N3 + h * DH;
    const __half* kbase = qbase + D_RES;
    const __half* vbase = qbase + 2 * D_RES;
    __half* Zb = Z + (size_t)b * SEQ * D_RES + h * DH;

    const uint32_t ab0 = (uint32_t)(((w * 16 + (lane & 15)) * STRH
                                     + ((lane >> 4) << 3)) * 2);

    #pragma unroll 1
    for (int hf = 0; hf < 2; hf++) {
        int qt = hf ? (15 - (int)blockIdx.x) : (int)blockIdx.x;
        if (hf) __syncthreads();   /* previous half's smem reads done */

        stage_tile_h<128, 256>(sQ, qbase + (size_t)qt * 128 * N3, N3, 0);
        stage_tile_h<64, 256>(sK0, kbase, N3, 0);
        stage_tile_h<64, 256>(sV0, vbase, N3, 0);
        CP_COMMIT();

        int nkt = 2 * qt + 2;
        float m_i[2] = { -1e30f, -1e30f }, l_i[2] = { 0.f, 0.f };
        float oacc[8][4] = {};

        #pragma unroll 1
        for (int kt2 = 0; kt2 < nkt; kt2++) {
            CP_WAIT0();
            __syncthreads();
            uint32_t sK = sK0 + (uint32_t)(kt2 & 1) * TK_B;
            uint32_t sV = sV0 + (uint32_t)(kt2 & 1) * TK_B;
            if (kt2 + 1 < nkt) {
                uint32_t alt = (uint32_t)((kt2 + 1) & 1) * TK_B;
                stage_tile_h<64, 256>(sK0 + alt, kbase + (size_t)(kt2 + 1) * 64 * N3, N3, 0);
                stage_tile_h<64, 256>(sV0 + alt, vbase + (size_t)(kt2 + 1) * 64 * N3, N3, 0);
                CP_COMMIT();
            }

            /* ---- S = Q K^T ---- */
            float sacc[8][4] = {};
            {
                uint32_t ab = sQ + ab0;
                uint32_t bb = sK + (uint32_t)((((lane & 15)) * STRH
                                               + ((lane >> 4) << 3)) * 2);
                #pragma unroll
                for (int ks = 0; ks < 4; ks++) {
                    uint32_t af[4];
                    ldsm4(ab + ks * 32, af[0], af[1], af[2], af[3]);
                    uint32_t bf[8][2];
                    #pragma unroll
                    for (int p = 0; p < 4; p++) {
                        uint32_t r0, r1, r2, r3;
                        ldsm4(bb + p * (16 * STRH * 2) + ks * 32, r0, r1, r2, r3);
                        bf[2 * p][0] = r0; bf[2 * p][1] = r2;
                        bf[2 * p + 1][0] = r1; bf[2 * p + 1][1] = r3;
                    }
                    #pragma unroll
                    for (int nt = 0; nt < 8; nt++)
                        mma_f16(sacc[nt], af, bf[nt][0], bf[nt][1]);
                }
            }

            /* ---- scale + causal mask ---- */
            int rg = qt * 128 + w * 16 + (lane >> 2);
            int cg0 = kt2 * 64 + 2 * (lane & 3);
            bool diag = (kt2 >= 2 * qt);
            #pragma unroll
            for (int nt = 0; nt < 8; nt++)
                #pragma unroll
                for (int hh = 0; hh < 2; hh++) {
                    int r = rg + 8 * hh;
                    int c = cg0 + nt * 8;
                    float v0 = sacc[nt][2 * hh] * 0.125f;
                    float v1 = sacc[nt][2 * hh + 1] * 0.125f;
                    if (diag) {
                        if (c > r)     v0 = -1e30f;
                        if (c + 1 > r) v1 = -1e30f;
                    }
                    sacc[nt][2 * hh] = v0;
                    sacc[nt][2 * hh + 1] = v1;
                }

            /* ---- row max (quad shfl only) ---- */
            float m_new[2], alpha[2];
            #pragma unroll
            for (int hh = 0; hh < 2; hh++) {
                float v = -1e30f;
                #pragma unroll
                for (int nt = 0; nt < 8; nt++) {
                    v = fmaxf(v, sacc[nt][2 * hh]);
                    v = fmaxf(v, sacc[nt][2 * hh + 1]);
                }
                v = fmaxf(v, __shfl_xor_sync(0xffffffffu, v, 1));
                v = fmaxf(v, __shfl_xor_sync(0xffffffffu, v, 2));
                m_new[hh] = fmaxf(m_i[hh], v);
                alpha[hh] = __expf(m_i[hh] - m_new[hh]);
                m_i[hh] = m_new[hh];
            }

            /* ---- P = exp(S - m) in registers ---- */
            uint32_t ph[8][2];
            float rs[2] = { 0.f, 0.f };
            #pragma unroll
            for (int nt = 0; nt < 8; nt++)
                #pragma unroll
                for (int hh = 0; hh < 2; hh++) {
                    float p0 = __expf(sacc[nt][2 * hh] - m_new[hh]);
                    float p1 = __expf(sacc[nt][2 * hh + 1] - m_new[hh]);
                    rs[hh] += p0 + p1;
                    __half2 hp = __floats2half2_rn(p0, p1);
                    ph[nt][hh] = *(uint32_t*)&hp;
                }
            #pragma unroll
            for (int hh = 0; hh < 2; hh++) {
                float s2 = rs[hh];
                s2 += __shfl_xor_sync(0xffffffffu, s2, 1);
                s2 += __shfl_xor_sync(0xffffffffu, s2, 2);
                l_i[hh] = l_i[hh] * alpha[hh] + s2;
                #pragma unroll
                for (int nt = 0; nt < 8; nt++) {
                    oacc[nt][2 * hh]     *= alpha[hh];
                    oacc[nt][2 * hh + 1] *= alpha[hh];
                }
            }

            /* ---- O += P V ---- */
            {
                uint32_t vb = sV + (uint32_t)(((lane & 15) * STRH
                                               + ((lane >> 4) << 3)) * 2);
                #pragma unroll
                for (int ks = 0; ks < 4; ks++) {
                    uint32_t af[4] = { ph[2 * ks][0], ph[2 * ks][1],
                                       ph[2 * ks + 1][0], ph[2 * ks + 1][1] };
                    uint32_t vf[8][2];
                    #pragma unroll
                    for (int p = 0; p < 4; p++) {
                        uint32_t r0, r1, r2, r3;
                        ldsm4t(vb + (uint32_t)((ks * 16 * STRH + p * 16) * 2),
                               r0, r1, r2, r3);
                        vf[2 * p][0] = r0; vf[2 * p][1] = r1;
                        vf[2 * p + 1][0] = r2; vf[2 * p + 1][1] = r3;
                    }
                    #pragma unroll
                    for (int nt = 0; nt < 8; nt++)
                        mma_f16(oacc[nt], af, vf[nt][0], vf[nt][1]);
                }
            }
        }

        /* ---- Z = O / l ---- */
        #pragma unroll
        for (int hh = 0; hh < 2; hh++) {
            float inv = 1.f / l_i[hh];
            int row = qt * 128 + w * 16 + (lane >> 2) + 8 * hh;
            #pragma unroll
            for (int nt = 0; nt < 8; nt++) {
                int col = nt * 8 + 2 * (lane & 3);
                *(__half2*)(Zb + (size_t)row * D_RES + col) =
                    __floats2half2_rn(oacc[nt][2 * hh] * inv,
                                      oacc[nt][2 * hh + 1] * inv);
            }
        }
    }
}

/* ------------------------------------------------------------------ */
/* LayerNorm: fp32 in -> half out (single pass)                        */
/* ------------------------------------------------------------------ */
__global__ void __launch_bounds__(256) layernorm_h_k(const float* __restrict__ in,
        const float* __restrict__ w, const float* __restrict__ b,
        __half* __restrict__ out) {
    int row = blockIdx.x, t = threadIdx.x;
    const float* x = in + (size_t)row * D_RES;
    float4 v = *(const float4*)(x + t * 4);
    float s = v.x + v.y + v.z + v.w;
    float q = v.x * v.x + v.y * v.y + v.z * v.z + v.w * v.w;
    #pragma unroll
    for (int o = 16; o > 0; o >>= 1) {
        s += __shfl_xor_sync(0xffffffffu, s, o);
        q += __shfl_xor_sync(0xffffffffu, q, o);
    }
    __shared__ float rs[8], rq[8];
    int wid = t >> 5;
    if ((t & 31) == 0) { rs[wid] = s; rq[wid] = q; }
    __syncthreads();
    s = rs[0] + rs[1] + rs[2] + rs[3] + rs[4] + rs[5] + rs[6] + rs[7];
    q = rq[0] + rq[1] + rq[2] + rq[3] + rq[4] + rq[5] + rq[6] + rq[7];
    float mean = s * (1.f / D_RES);
    float inv = rsqrtf(q * (1.f / D_RES) - mean * mean + EPSLN);
    float4 wv = *(const float4*)(w + t * 4);
    float4 bv = *(const float4*)(b + t * 4);
    __half* orow = out + (size_t)row * D_RES + t * 4;
    *(__half2*)(orow)     = __floats2half2_rn((v.x - mean) * inv * wv.x + bv.x,
                                              (v.y - mean) * inv * wv.y + bv.y);
    *(__half2*)(orow + 2) = __floats2half2_rn((v.z - mean) * inv * wv.z + bv.z,
                                              (v.w - mean) * inv * wv.w + bv.w);
}

/* ------------------------------------------------------------------ */
/* Weight prep                                                         */
/* ------------------------------------------------------------------ */
__global__ void pack_qkv_k(const float* __restrict__ WQ, const float* __restrict__ WK,
                           const float* __restrict__ WV, const float* __restrict__ bQ,
                           const float* __restrict__ bK, const float* __restrict__ bV) {
    int idx = blockIdx.x * blockDim.x + threadIdx.x;
    if (idx < D_RES * N3) {
        int d = idx / N3;
        int n = idx % N3;
        int sel = n / D_RES;
        int c = n % D_RES;
        int h = c / DH, e = c % DH;
        const float* W = (sel == 0) ? WQ : (sel == 1) ? WK : WV;
        g_Wqkv[idx] = __float2half_rn(W[((size_t)h * D_RES + d) * DH + e]);
    }
    if (idx < N3) {
        const float* bb = (idx < D_RES) ? bQ : (idx < 2 * D_RES) ? bK : bV;
        g_bias_qkv[idx] = bb[idx % D_RES];
    }
}

/* one kernel converting all three weight matrices fp32 -> fp16 */
#define CVT_N0 (D_RES * D_RES / 8)             /* WO   */
#define CVT_N1 (CVT_N0 + D_RES * DMLP / 8)     /* +Win */
#define CVT_N2 (CVT_N1 + DMLP * D_RES / 8)     /* +Wout*/
__global__ void __launch_bounds__(256) cvt_all_k(const float* __restrict__ WO,
        const float* __restrict__ Win, const float* __restrict__ Wout,
        __half* __restrict__ dWO, __half* __restrict__ dWin,
        __half* __restrict__ dWout) {
    int i = blockIdx.x * blockDim.x + threadIdx.x;
    if (i >= CVT_N2) return;
    const float* src;
    __half* dst;
    int j;
    if (i < CVT_N0)      { src = WO;   dst = dWO;   j = i; }
    else if (i < CVT_N1) { src = Win;  dst = dWin;  j = i - CVT_N0; }
    else                 { src = Wout; dst = dWout; j = i - CVT_N1; }
    float4 a = *(const float4*)(src + (size_t)j * 8);
    float4 b = *(const float4*)(src + (size_t)j * 8 + 4);
    __half2 h0 = __floats2half2_rn(a.x, a.y);
    __half2 h1 = __floats2half2_rn(a.z, a.w);
    __half2 h2 = __floats2half2_rn(b.x, b.y);
    __half2 h3 = __floats2half2_rn(b.z, b.w);
    uint4 o;
    o.x = *(uint32_t*)&h0; o.y = *(uint32_t*)&h1;
    o.z = *(uint32_t*)&h2; o.w = *(uint32_t*)&h3;
    *(uint4*)(dst + (size_t)j * 8) = o;
}

/* ------------------------------------------------------------------ */
/* Launch                                                              */
/* ------------------------------------------------------------------ */
extern "C" void kernel_launch(void* const* d_in, const int* in_sizes, int n_in,
                              void* d_out, int out_size) {
    const float* resid_pre = (const float*)d_in[0];
    const float* ln1_w = (const float*)d_in[1];
    const float* ln1_b = (const float*)d_in[2];
    const float* WQ = (const float*)d_in[3];
    const float* bQ = (const float*)d_in[4];
    const float* WK = (const float*)d_in[5];
    const float* bK = (const float*)d_in[6];
    const float* WV = (const float*)d_in[7];
    const float* bV = (const float*)d_in[8];
    const float* WO = (const float*)d_in[9];
    const float* bO = (const float*)d_in[10];
    const float* ln2_w = (const float*)d_in[11];
    const float* ln2_b = (const float*)d_in[12];
    const float* Win  = (const float*)d_in[13];
    const float* bin  = (const float*)d_in[14];
    const float* Wout = (const float*)d_in[15];
    const float* bout = (const float*)d_in[16];
    float* out = (float*)d_out;

    __half *p_Wqkv, *p_WOh, *p_Winh, *p_Wouth, *p_xln, *p_qkv, *p_z, *p_y, *p_post;
    float *p_bias, *p_mid;
    cudaGetSymbolAddress((void**)&p_Wqkv, g_Wqkv);
    cudaGetSymbolAddress((void**)&p_bias, g_bias_qkv);
    cudaGetSymbolAddress((void**)&p_WOh, g_WOh);
    cudaGetSymbolAddress((void**)&p_Winh, g_Winh);
    cudaGetSymbolAddress((void**)&p_Wouth, g_Wouth);
    cudaGetSymbolAddress((void**)&p_xln, g_xln);
    cudaGetSymbolAddress((void**)&p_qkv, g_qkv);
    cudaGetSymbolAddress((void**)&p_z, g_z);
    cudaGetSymbolAddress((void**)&p_mid, g_resid_mid);
    cudaGetSymbolAddress((void**)&p_y, g_y);
    cudaGetSymbolAddress((void**)&p_post, g_post);

    cudaFuncSetAttribute(h_gemm_k<EPI_BIAS, true>,
                         cudaFuncAttributeMaxDynamicSharedMemorySize, SMEM_DENSE);
    cudaFuncSetAttribute(h_gemm_k<EPI_BIAS_RES, false>,
                         cudaFuncAttributeMaxDynamicSharedMemorySize, SMEM_DENSE);
    cudaFuncSetAttribute(h_gemm_k<EPI_BIAS_GELU, true>,
                         cudaFuncAttributeMaxDynamicSharedMemorySize, SMEM_DENSE);
    cudaFuncSetAttribute(flash_k,
                         cudaFuncAttributeMaxDynamicSharedMemorySize, FLASH_SMEM);

    /* weight prep */
    pack_qkv_k<<<(D_RES * N3 + 255) / 256, 256>>>(WQ, WK, WV, bQ, bK, bV);
    cvt_all_k<<<(CVT_N2 + 255) / 256, 256>>>(WO, Win, Wout, p_WOh, p_Winh, p_Wouth);

    /* LN1 (fp32 -> half) */
    layernorm_h_k<<<NTOK, 256>>>(resid_pre, ln1_w, ln1_b, p_xln);

    /* QKV = xln @ Wqkv + bias -> half */
    h_gemm_k<EPI_BIAS, true><<<dim3(N3 / 128, NTOK / 128), 256, SMEM_DENSE>>>(
        p_xln, D_RES, p_Wqkv, N3, p_qkv, N3, D_RES, p_bias, nullptr, 0);

    /* fused attention (FA2 layout, V consumed in-place) */
    flash_k<<<dim3(8, BATCH * NH), 256, FLASH_SMEM>>>(p_qkv, p_z);

    /* resid_mid = Z @ W_O + b_O + resid_pre -> fp32 */
    h_gemm_k<EPI_BIAS_RES, false><<<dim3(D_RES / 128, NTOK / 128), 256, SMEM_DENSE>>>(
        p_z, D_RES, p_WOh, D_RES, p_mid, D_RES, D_RES, bO, resid_pre, D_RES);

    /* LN2 (fp32 -> half) */
    layernorm_h_k<<<NTOK, 256>>>(p_mid, ln2_w, ln2_b, p_y);

    /* post = gelu(y @ W_in + b_in) -> half */
    h_gemm_k<EPI_BIAS_GELU, true><<<dim3(DMLP / 128, NTOK / 128), 256, SMEM_DENSE>>>(
        p_y, D_RES, p_Winh, DMLP, p_post, DMLP, D_RES, bin, nullptr, 0);

    /* out = post @ W_out + b_out + resid_mid -> fp32 */
    h_gemm_k<EPI_BIAS_RES, false><<<dim3(D_RES / 128, NTOK / 128), 256, SMEM_DENSE>>>(
        p_post, DMLP, p_Wouth, D_RES, out, D_RES, DMLP, bout, p_mid, D_RES);
}

// round 17
// speedup vs baseline: 1.0572x; 1.0126x over previous
#include <cuda_runtime.h>
#include <cuda_fp16.h>
#include <math.h>
#include <stdint.h>

#define D_RES  1024
#define NH     16
#define DH     64
#define DMLP   4096
#define SEQ    2048
#define BATCH  2
#define NTOK   (BATCH*SEQ)      /* 4096 */
#define N3     (3*D_RES)        /* 3072 */
#define EPSLN  1e-5f
#define L2E8   0.1803368801111f /* log2(e)/8 : folds 1/sqrt(64) and ln->log2 */

/* ------------------------------------------------------------------ */
/* Scratch: __device__ globals                                         */
/* ------------------------------------------------------------------ */
__device__ __half g_Wqkv[D_RES * N3];                /* [1024][3072] k-major */
__device__ float  g_bias_qkv[N3];
__device__ __half g_WOh[D_RES * D_RES];              /* [1024][1024] natural */
__device__ __half g_Winh[D_RES * DMLP];              /* [1024][4096] natural */
__device__ __half g_Wouth[DMLP * D_RES];             /* [4096][1024] natural */
__device__ __half g_xln[(size_t)NTOK * D_RES];
__device__ __half g_qkv[(size_t)NTOK * N3];
__device__ __half g_z[(size_t)NTOK * D_RES];
__device__ float  g_resid_mid[(size_t)NTOK * D_RES];
__device__ __half g_y[(size_t)NTOK * D_RES];
__device__ __half g_post[(size_t)NTOK * DMLP];

/* ------------------------------------------------------------------ */
/* PTX helpers                                                         */
/* ------------------------------------------------------------------ */
__device__ __forceinline__ uint32_t smem_u32(const void* p) {
    uint32_t a;
    asm("{ .reg .u64 t; cvta.to.shared.u64 t, %1; cvt.u32.u64 %0, t; }" : "=r"(a) : "l"(p));
    return a;
}
/* .ca: L1 allocation gives cross-CTA reuse on same SM (R15 lesson) */
__device__ __forceinline__ void cp16(uint32_t dst, const void* src) {
    asm volatile("cp.async.ca.shared.global [%0], [%1], 16;" :: "r"(dst), "l"(src));
}
#define CP_COMMIT()  asm volatile("cp.async.commit_group;" ::: "memory")
#define CP_WAIT0()   asm volatile("cp.async.wait_group 0;" ::: "memory")

__device__ __forceinline__ void ldsm4(uint32_t a, uint32_t& r0, uint32_t& r1,
                                      uint32_t& r2, uint32_t& r3) {
    asm volatile("ldmatrix.sync.aligned.m8n8.x4.shared.b16 {%0,%1,%2,%3}, [%4];"
                 : "=r"(r0), "=r"(r1), "=r"(r2), "=r"(r3) : "r"(a));
}
__device__ __forceinline__ void ldsm4t(uint32_t a, uint32_t& r0, uint32_t& r1,
                                       uint32_t& r2, uint32_t& r3) {
    asm volatile("ldmatrix.sync.aligned.m8n8.x4.trans.shared.b16 {%0,%1,%2,%3}, [%4];"
                 : "=r"(r0), "=r"(r1), "=r"(r2), "=r"(r3) : "r"(a));
}
__device__ __forceinline__ void mma_f16(float* c, const uint32_t* a,
                                        uint32_t b0, uint32_t b1) {
    asm volatile("mma.sync.aligned.m16n8k16.row.col.f32.f16.f16.f32 "
                 "{%0,%1,%2,%3}, {%4,%5,%6,%7}, {%8,%9}, {%0,%1,%2,%3};"
                 : "+f"(c[0]), "+f"(c[1]), "+f"(c[2]), "+f"(c[3])
                 : "r"(a[0]), "r"(a[1]), "r"(a[2]), "r"(a[3]), "r"(b0), "r"(b1));
}
/* packed half2 exp2 (ex2.approx.f16x2, sm_75+) */
__device__ __forceinline__ uint32_t h2exp2_u32(uint32_t x) {
    uint32_t r;
    asm("ex2.approx.f16x2 %0, %1;" : "=r"(r) : "r"(x));
    return r;
}

/* ------------------------------------------------------------------ */
/* Layouts:                                                            */
/*   A tiles / K / V tiles: ROWS x 64 halves, stride 72 (144 B)        */
/*   dense B tiles: 64 k-rows x 128 n halves, stride 136 (272 B)       */
/* ------------------------------------------------------------------ */
#define STRH 72
#define STRB 136
#define TILE_A_B (128 * STRH * 2)      /* 18432 B */
#define TILE_B_B (64 * STRB * 2)       /* 17408 B */
#define TK_B     (64 * STRH * 2)       /* 9216 B (flash K/V tile) */

/* A-style tile: ROWS x 64 halves, stride 72 */
template <int ROWS, int NT>
__device__ __forceinline__ void stage_tile_h(uint32_t s, const __half* __restrict__ g,
                                             int ld, int k0) {
    #pragma unroll
    for (int i = 0; i < (ROWS * 8) / NT; i++) {
        int u = threadIdx.x + i * NT;
        int r = u >> 3, c = u & 7;
        cp16(s + (uint32_t)((r * STRH + c * 8) * 2), g + (size_t)r * ld + k0 + c * 8);
    }
}

/* dense k-major B tile: 64 k-rows x 128 n halves, stride 136.          */
__device__ __forceinline__ void stage_tile_b(uint32_t s, const __half* __restrict__ g,
                                             int ld, int k0) {
    #pragma unroll
    for (int i = 0; i < 4; i++) {
        int u = threadIdx.x + i * 256;
        int r = u >> 4, c = u & 15;
        cp16(s + (uint32_t)((r * STRB + c * 8) * 2),
             g + (size_t)(k0 + r) * ld + c * 8);
    }
}

/* ---------------- MMA chunk, k-major B (trans ldmatrix) ------------ */
template <int MT, int NT, int WN, int BSTR>
__device__ __forceinline__ void compute_chunk_bt(uint32_t a_s, uint32_t b_s,
                                                 float (&acc)[MT][NT][4]) {
    int lane = threadIdx.x & 31, wid = threadIdx.x >> 5;
    int wm = wid / WN, wn = wid % WN;
    uint32_t ab = a_s + (uint32_t)(((wm * (MT * 16) + (lane & 15)) * STRH
                                    + ((lane >> 4) << 3)) * 2);
    uint32_t bb = b_s + (uint32_t)(((lane & 15) * BSTR
                                    + wn * (NT * 8) + ((lane >> 4) << 3)) * 2);
    #pragma unroll
    for (int ks = 0; ks < 4; ks++) {
        uint32_t af[MT][4], bf[NT][2];
        #pragma unroll
        for (int mt = 0; mt < MT; mt++)
            ldsm4(ab + mt * (16 * STRH * 2) + ks * 32,
                  af[mt][0], af[mt][1], af[mt][2], af[mt][3]);
        #pragma unroll
        for (int p = 0; p < NT / 2; p++) {
            uint32_t r0, r1, r2, r3;
            ldsm4t(bb + (uint32_t)((ks * 16 * BSTR + p * 16) * 2), r0, r1, r2, r3);
            bf[2 * p][0] = r0; bf[2 * p][1] = r1;
            bf[2 * p + 1][0] = r2; bf[2 * p + 1][1] = r3;
        }
        #pragma unroll
        for (int mt = 0; mt < MT; mt++)
            #pragma unroll
            for (int nt = 0; nt < NT; nt++)
                mma_f16(acc[mt][nt], af[mt], bf[nt][0], bf[nt][1]);
    }
}

/* ------------------------------------------------------------------ */
/* Dense GEMM: double-buffer, K-chunk 64, SINGLE barrier per chunk     */
/* smem = 2 * (18432 + 17408) = 71680 B -> 2 CTAs/SM                   */
/* ------------------------------------------------------------------ */
#define STAGE_B (TILE_A_B + TILE_B_B)
#define SMEM_DENSE (2 * STAGE_B)

__device__ __forceinline__ void mma_run_dense(uint32_t sb,
        const __half* __restrict__ A, int lda,
        const __half* __restrict__ Bn, int ldb, int nc, float (&acc)[4][4][4]) {
    uint32_t aS[2] = { sb, sb + STAGE_B };
    uint32_t bS[2] = { sb + TILE_A_B, sb + STAGE_B + TILE_A_B };

    stage_tile_h<128, 256>(aS[0], A, lda, 0);
    stage_tile_b(bS[0], Bn, ldb, 0);
    CP_COMMIT();

    for (int c = 0; c < nc; c++) {
        CP_WAIT0();
        __syncthreads();
        if (c + 1 < nc) {
            int nb = (c + 1) & 1;
            stage_tile_h<128, 256>(aS[nb], A, lda, (c + 1) * 64);
            stage_tile_b(bS[nb], Bn, ldb, (c + 1) * 64);
            CP_COMMIT();
        }
        compute_chunk_bt<4, 4, 4, STRB>(aS[c & 1], bS[c & 1], acc);
    }
}

__device__ __forceinline__ float gelu_exact(float x) {
    return 0.5f * x * (1.f + erff(x * 0.70710678118654752f));
}

enum { EPI_BIAS = 1, EPI_BIAS_RES = 2, EPI_BIAS_GELU = 3 };

template <int EPI, bool HOUT>
__device__ __forceinline__ void epilogue_dense_h(float (&acc)[4][4][4],
        void* __restrict__ Cv, int ldc, int bm, int bn,
        const float* __restrict__ bias, const float* __restrict__ res, int ldres) {
    int lane = threadIdx.x & 31, wid = threadIdx.x >> 5;
    int wm = wid >> 2, wn = wid & 3;
    int r0 = bm + wm * 64 + (lane >> 2);
    int c0 = bn + wn * 32 + 2 * (lane & 3);
    #pragma unroll
    for (int mt = 0; mt < 4; mt++) {
        #pragma unroll
        for (int nt = 0; nt < 4; nt++) {
            int col = c0 + nt * 8;
            float2 bb = *(const float2*)(bias + col);
            #pragma unroll
            for (int h = 0; h < 2; h++) {
                int row = r0 + mt * 16 + h * 8;
                float v0 = acc[mt][nt][2 * h] + bb.x;
                float v1 = acc[mt][nt][2 * h + 1] + bb.y;
                if (EPI == EPI_BIAS_RES) {
                    float2 rr = *(const float2*)(res + (size_t)row * ldres + col);
                    v0 += rr.x; v1 += rr.y;
                }
                if (EPI == EPI_BIAS_GELU) { v0 = gelu_exact(v0); v1 = gelu_exact(v1); }
                if (HOUT) {
                    *(__half2*)((__half*)Cv + (size_t)row * ldc + col) =
                        __floats2half2_rn(v0, v1);
                } else {
                    *(float2*)((float*)Cv + (size_t)row * ldc + col) =
                        make_float2(v0, v1);
                }
            }
        }
    }
}

template <int EPI, bool HOUT>
__global__ void __launch_bounds__(256, 2) h_gemm_k(const __half* __restrict__ A, int lda,
        const __half* __restrict__ Bn, int ldb, void* __restrict__ C, int ldc, int K,
        const float* __restrict__ bias, const float* __restrict__ res, int ldres) {
    extern __shared__ __half smh[];
    uint32_t sb = smem_u32(smh);
    int bm = blockIdx.y * 128, bn = blockIdx.x * 128;
    float acc[4][4][4] = {};
    mma_run_dense(sb, A + (size_t)bm * lda, lda, Bn + bn, ldb, K / 64, acc);
    epilogue_dense_h<EPI, HOUT>(acc, C, ldc, bm, bn, bias, res, ldres);
}

/* ------------------------------------------------------------------ */
/* Flash attention, FA2 layout; softmax in log2 domain, fp16x2 exp2    */
/* ------------------------------------------------------------------ */
#define FLASH_SMEM (TILE_A_B + 4 * TK_B)

__global__ void __launch_bounds__(256, 2) flash_k(const __half* __restrict__ qkv,
                                                  __half* __restrict__ Z) {
    extern __shared__ __half smh[];
    uint32_t sb = smem_u32(smh);
    const uint32_t sQ  = sb;
    const uint32_t sK0 = sb + TILE_A_B;
    const uint32_t sV0 = sb + TILE_A_B + 2 * TK_B;

    int bh = blockIdx.y, b = bh >> 4, h = bh & 15;
    int lane = threadIdx.x & 31, w = threadIdx.x >> 5;

    const __half* qbase = qkv + (size_t)b * SEQ * N3 + h * DH;
    const __half* kbase = qbase + D_RES;
    const __half* vbase = qbase + 2 * D_RES;
    __half* Zb = Z + (size_t)b * SEQ * D_RES + h * DH;

    const uint32_t ab0 = (uint32_t)(((w * 16 + (lane & 15)) * STRH
                                     + ((lane >> 4) << 3)) * 2);

    #pragma unroll 1
    for (int hf = 0; hf < 2; hf++) {
        int qt = hf ? (15 - (int)blockIdx.x) : (int)blockIdx.x;
        if (hf) __syncthreads();   /* previous half's smem reads done */

        stage_tile_h<128, 256>(sQ, qbase + (size_t)qt * 128 * N3, N3, 0);
        stage_tile_h<64, 256>(sK0, kbase, N3, 0);
        stage_tile_h<64, 256>(sV0, vbase, N3, 0);
        CP_COMMIT();

        int nkt = 2 * qt + 2;
        float m_i[2] = { -1e30f, -1e30f }, l_i[2] = { 0.f, 0.f };
        float oacc[8][4] = {};

        #pragma unroll 1
        for (int kt2 = 0; kt2 < nkt; kt2++) {
            CP_WAIT0();
            __syncthreads();
            uint32_t sK = sK0 + (uint32_t)(kt2 & 1) * TK_B;
            uint32_t sV = sV0 + (uint32_t)(kt2 & 1) * TK_B;
            if (kt2 + 1 < nkt) {
                uint32_t alt = (uint32_t)((kt2 + 1) & 1) * TK_B;
                stage_tile_h<64, 256>(sK0 + alt, kbase + (size_t)(kt2 + 1) * 64 * N3, N3, 0);
                stage_tile_h<64, 256>(sV0 + alt, vbase + (size_t)(kt2 + 1) * 64 * N3, N3, 0);
                CP_COMMIT();
            }

            /* ---- S = Q K^T ---- */
            float sacc[8][4] = {};
            {
                uint32_t ab = sQ + ab0;
                uint32_t bb = sK + (uint32_t)((((lane & 15)) * STRH
                                               + ((lane >> 4) << 3)) * 2);
                #pragma unroll
                for (int ks = 0; ks < 4; ks++) {
                    uint32_t af[4];
                    ldsm4(ab + ks * 32, af[0], af[1], af[2], af[3]);
                    uint32_t bf[8][2];
                    #pragma unroll
                    for (int p = 0; p < 4; p++) {
                        uint32_t r0, r1, r2, r3;
                        ldsm4(bb + p * (16 * STRH * 2) + ks * 32, r0, r1, r2, r3);
                        bf[2 * p][0] = r0; bf[2 * p][1] = r2;
                        bf[2 * p + 1][0] = r1; bf[2 * p + 1][1] = r3;
                    }
                    #pragma unroll
                    for (int nt = 0; nt < 8; nt++)
                        mma_f16(sacc[nt], af, bf[nt][0], bf[nt][1]);
                }
            }

            /* ---- to log2 domain (scale folded) + causal mask ---- */
            int rg = qt * 128 + w * 16 + (lane >> 2);
            int cg0 = kt2 * 64 + 2 * (lane & 3);
            bool diag = (kt2 >= 2 * qt);
            #pragma unroll
            for (int nt = 0; nt < 8; nt++)
                #pragma unroll
                for (int hh = 0; hh < 2; hh++) {
                    int r = rg + 8 * hh;
                    int c = cg0 + nt * 8;
                    float v0 = sacc[nt][2 * hh] * L2E8;
                    float v1 = sacc[nt][2 * hh + 1] * L2E8;
                    if (diag) {
                        if (c > r)     v0 = -1e30f;
                        if (c + 1 > r) v1 = -1e30f;
                    }
                    sacc[nt][2 * hh] = v0;
                    sacc[nt][2 * hh + 1] = v1;
                }

            /* ---- row max (quad shfl only), log2 domain ---- */
            float m_new[2], alpha[2];
            #pragma unroll
            for (int hh = 0; hh < 2; hh++) {
                float v = -1e30f;
                #pragma unroll
                for (int nt = 0; nt < 8; nt++) {
                    v = fmaxf(v, sacc[nt][2 * hh]);
                    v = fmaxf(v, sacc[nt][2 * hh + 1]);
                }
                v = fmaxf(v, __shfl_xor_sync(0xffffffffu, v, 1));
                v = fmaxf(v, __shfl_xor_sync(0xffffffffu, v, 2));
                m_new[hh] = fmaxf(m_i[hh], v);
                alpha[hh] = exp2f(m_i[hh] - m_new[hh]);
                m_i[hh] = m_new[hh];
            }

            /* ---- P = exp2(t - m) via packed fp16x2 ---- */
            uint32_t ph[8][2];
            float rs[2] = { 0.f, 0.f };
            #pragma unroll
            for (int nt = 0; nt < 8; nt++)
                #pragma unroll
                for (int hh = 0; hh < 2; hh++) {
                    float d0 = sacc[nt][2 * hh] - m_new[hh];
                    float d1 = sacc[nt][2 * hh + 1] - m_new[hh];
                    __half2 hd = __floats2half2_rn(d0, d1);
                    uint32_t hp = h2exp2_u32(*(uint32_t*)&hd);
                    ph[nt][hh] = hp;
                    float2 pf = __half22float2(*(__half2*)&hp);
                    rs[hh] += pf.x + pf.y;
                }
            #pragma unroll
            for (int hh = 0; hh < 2; hh++) {
                float s2 = rs[hh];
                s2 += __shfl_xor_sync(0xffffffffu, s2, 1);
                s2 += __shfl_xor_sync(0xffffffffu, s2, 2);
                l_i[hh] = l_i[hh] * alpha[hh] + s2;
                #pragma unroll
                for (int nt = 0; nt < 8; nt++) {
                    oacc[nt][2 * hh]     *= alpha[hh];
                    oacc[nt][2 * hh + 1] *= alpha[hh];
                }
            }

            /* ---- O += P V ---- */
            {
                uint32_t vb = sV + (uint32_t)(((lane & 15) * STRH
                                               + ((lane >> 4) << 3)) * 2);
                #pragma unroll
                for (int ks = 0; ks < 4; ks++) {
                    uint32_t af[4] = { ph[2 * ks][0], ph[2 * ks][1],
                                       ph[2 * ks + 1][0], ph[2 * ks + 1][1] };
                    uint32_t vf[8][2];
                    #pragma unroll
                    for (int p = 0; p < 4; p++) {
                        uint32_t r0, r1, r2, r3;
                        ldsm4t(vb + (uint32_t)((ks * 16 * STRH + p * 16) * 2),
                               r0, r1, r2, r3);
                        vf[2 * p][0] = r0; vf[2 * p][1] = r1;
                        vf[2 * p + 1][0] = r2; vf[2 * p + 1][1] = r3;
                    }
                    #pragma unroll
                    for (int nt = 0; nt < 8; nt++)
                        mma_f16(oacc[nt], af, vf[nt][0], vf[nt][1]);
                }
            }
        }

        /* ---- Z = O / l ---- */
        #pragma unroll
        for (int hh = 0; hh < 2; hh++) {
            float inv = 1.f / l_i[hh];
            int row = qt * 128 + w * 16 + (lane >> 2) + 8 * hh;
            #pragma unroll
            for (int nt = 0; nt < 8; nt++) {
                int col = nt * 8 + 2 * (lane & 3);
                *(__half2*)(Zb + (size_t)row * D_RES + col) =
                    __floats2half2_rn(oacc[nt][2 * hh] * inv,
                                      oacc[nt][2 * hh + 1] * inv);
            }
        }
    }
}

/* ------------------------------------------------------------------ */
/* LayerNorm: fp32 in -> half out (single pass)                        */
/* ------------------------------------------------------------------ */
__global__ void __launch_bounds__(256) layernorm_h_k(const float* __restrict__ in,
        const float* __restrict__ w, const float* __restrict__ b,
        __half* __restrict__ out) {
    int row = blockIdx.x, t = threadIdx.x;
    const float* x = in + (size_t)row * D_RES;
    float4 v = *(const float4*)(x + t * 4);
    float s = v.x + v.y + v.z + v.w;
    float q = v.x * v.x + v.y * v.y + v.z * v.z + v.w * v.w;
    #pragma unroll
    for (int o = 16; o > 0; o >>= 1) {
        s += __shfl_xor_sync(0xffffffffu, s, o);
        q += __shfl_xor_sync(0xffffffffu, q, o);
    }
    __shared__ float rs[8], rq[8];
    int wid = t >> 5;
    if ((t & 31) == 0) { rs[wid] = s; rq[wid] = q; }
    __syncthreads();
    s = rs[0] + rs[1] + rs[2] + rs[3] + rs[4] + rs[5] + rs[6] + rs[7];
    q = rq[0] + rq[1] + rq[2] + rq[3] + rq[4] + rq[5] + rq[6] + rq[7];
    float mean = s * (1.f / D_RES);
    float inv = rsqrtf(q * (1.f / D_RES) - mean * mean + EPSLN);
    float4 wv = *(const float4*)(w + t * 4);
    float4 bv = *(const float4*)(b + t * 4);
    __half* orow = out + (size_t)row * D_RES + t * 4;
    *(__half2*)(orow)     = __floats2half2_rn((v.x - mean) * inv * wv.x + bv.x,
                                              (v.y - mean) * inv * wv.y + bv.y);
    *(__half2*)(orow + 2) = __floats2half2_rn((v.z - mean) * inv * wv.z + bv.z,
                                              (v.w - mean) * inv * wv.w + bv.w);
}

/* ------------------------------------------------------------------ */
/* Fused weight prep: QKV pack + bias + 3x fp32->fp16 convert          */
/* ------------------------------------------------------------------ */
#define PACK_BLK ((D_RES * N3 + 255) / 256)
#define CVT_N0 (D_RES * D_RES / 8)             /* WO   */
#define CVT_N1 (CVT_N0 + D_RES * DMLP / 8)     /* +Win */
#define CVT_N2 (CVT_N1 + DMLP * D_RES / 8)     /* +Wout*/
#define CVT_BLK ((CVT_N2 + 255) / 256)

__global__ void __launch_bounds__(256) prep_k(
        const float* __restrict__ WQ, const float* __restrict__ WK,
        const float* __restrict__ WV, const float* __restrict__ bQ,
        const float* __restrict__ bK, const float* __restrict__ bV,
        const float* __restrict__ WO, const float* __restrict__ Win,
        const float* __restrict__ Wout,
        __half* __restrict__ dWO, __half* __restrict__ dWin,
        __half* __restrict__ dWout) {
    if (blockIdx.x < PACK_BLK) {
        int idx = blockIdx.x * 256 + threadIdx.x;
        if (idx < D_RES * N3) {
            int d = idx / N3;
            int n = idx % N3;
            int sel = n / D_RES;
            int c = n % D_RES;
            int h = c / DH, e = c % DH;
            const float* W = (sel == 0) ? WQ : (sel == 1) ? WK : WV;
            g_Wqkv[idx] = __float2half_rn(W[((size_t)h * D_RES + d) * DH + e]);
        }
        if (idx < N3) {
            const float* bb = (idx < D_RES) ? bQ : (idx < 2 * D_RES) ? bK : bV;
            g_bias_qkv[idx] = bb[idx % D_RES];
        }
    } else {
        int i = (blockIdx.x - PACK_BLK) * 256 + threadIdx.x;
        if (i >= CVT_N2) return;
        const float* src;
        __half* dst;
        int j;
        if (i < CVT_N0)      { src = WO;   dst = dWO;   j = i; }
        else if (i < CVT_N1) { src = Win;  dst = dWin;  j = i - CVT_N0; }
        else                 { src = Wout; dst = dWout; j = i - CVT_N1; }
        float4 a = *(const float4*)(src + (size_t)j * 8);
        float4 b = *(const float4*)(src + (size_t)j * 8 + 4);
        __half2 h0 = __floats2half2_rn(a.x, a.y);
        __half2 h1 = __floats2half2_rn(a.z, a.w);
        __half2 h2 = __floats2half2_rn(b.x, b.y);
        __half2 h3 = __floats2half2_rn(b.z, b.w);
        uint4 o;
        o.x = *(uint32_t*)&h0; o.y = *(uint32_t*)&h1;
        o.z = *(uint32_t*)&h2; o.w = *(uint32_t*)&h3;
        *(uint4*)(dst + (size_t)j * 8) = o;
    }
}

/* ------------------------------------------------------------------ */
/* Launch                                                              */
/* ------------------------------------------------------------------ */
extern "C" void kernel_launch(void* const* d_in, const int* in_sizes, int n_in,
                              void* d_out, int out_size) {
    const float* resid_pre = (const float*)d_in[0];
    const float* ln1_w = (const float*)d_in[1];
    const float* ln1_b = (const float*)d_in[2];
    const float* WQ = (const float*)d_in[3];
    const float* bQ = (const float*)d_in[4];
    const float* WK = (const float*)d_in[5];
    const float* bK = (const float*)d_in[6];
    const float* WV = (const float*)d_in[7];
    const float* bV = (const float*)d_in[8];
    const float* WO = (const float*)d_in[9];
    const float* bO = (const float*)d_in[10];
    const float* ln2_w = (const float*)d_in[11];
    const float* ln2_b = (const float*)d_in[12];
    const float* Win  = (const float*)d_in[13];
    const float* bin  = (const float*)d_in[14];
    const float* Wout = (const float*)d_in[15];
    const float* bout = (const float*)d_in[16];
    float* out = (float*)d_out;

    __half *p_Wqkv, *p_WOh, *p_Winh, *p_Wouth, *p_xln, *p_qkv, *p_z, *p_y, *p_post;
    float *p_bias, *p_mid;
    cudaGetSymbolAddress((void**)&p_Wqkv, g_Wqkv);
    cudaGetSymbolAddress((void**)&p_bias, g_bias_qkv);
    cudaGetSymbolAddress((void**)&p_WOh, g_WOh);
    cudaGetSymbolAddress((void**)&p_Winh, g_Winh);
    cudaGetSymbolAddress((void**)&p_Wouth, g_Wouth);
    cudaGetSymbolAddress((void**)&p_xln, g_xln);
    cudaGetSymbolAddress((void**)&p_qkv, g_qkv);
    cudaGetSymbolAddress((void**)&p_z, g_z);
    cudaGetSymbolAddress((void**)&p_mid, g_resid_mid);
    cudaGetSymbolAddress((void**)&p_y, g_y);
    cudaGetSymbolAddress((void**)&p_post, g_post);

    cudaFuncSetAttribute(h_gemm_k<EPI_BIAS, true>,
                         cudaFuncAttributeMaxDynamicSharedMemorySize, SMEM_DENSE);
    cudaFuncSetAttribute(h_gemm_k<EPI_BIAS_RES, false>,
                         cudaFuncAttributeMaxDynamicSharedMemorySize, SMEM_DENSE);
    cudaFuncSetAttribute(h_gemm_k<EPI_BIAS_GELU, true>,
                         cudaFuncAttributeMaxDynamicSharedMemorySize, SMEM_DENSE);
    cudaFuncSetAttribute(flash_k,
                         cudaFuncAttributeMaxDynamicSharedMemorySize, FLASH_SMEM);

    /* weight prep (single launch) */
    prep_k<<<PACK_BLK + CVT_BLK, 256>>>(WQ, WK, WV, bQ, bK, bV,
                                        WO, Win, Wout, p_WOh, p_Winh, p_Wouth);

    /* LN1 (fp32 -> half) */
    layernorm_h_k<<<NTOK, 256>>>(resid_pre, ln1_w, ln1_b, p_xln);

    /* QKV = xln @ Wqkv + bias -> half */
    h_gemm_k<EPI_BIAS, true><<<dim3(N3 / 128, NTOK / 128), 256, SMEM_DENSE>>>(
        p_xln, D_RES, p_Wqkv, N3, p_qkv, N3, D_RES, p_bias, nullptr, 0);

    /* fused attention (FA2 layout, V consumed in-place) */
    flash_k<<<dim3(8, BATCH * NH), 256, FLASH_SMEM>>>(p_qkv, p_z);

    /* resid_mid = Z @ W_O + b_O + resid_pre -> fp32 */
    h_gemm_k<EPI_BIAS_RES, false><<<dim3(D_RES / 128, NTOK / 128), 256, SMEM_DENSE>>>(
        p_z, D_RES, p_WOh, D_RES, p_mid, D_RES, D_RES, bO, resid_pre, D_RES);

    /* LN2 (fp32 -> half) */
    layernorm_h_k<<<NTOK, 256>>>(p_mid, ln2_w, ln2_b, p_y);

    /* post = gelu(y @ W_in + b_in) -> half */
    h_gemm_k<EPI_BIAS_GELU, true><<<dim3(DMLP / 128, NTOK / 128), 256, SMEM_DENSE>>>(
        p_y, D_RES, p_Winh, DMLP, p_post, DMLP, D_RES, bin, nullptr, 0);

    /* out = post @ W_out + b_out + resid_mid -> fp32 */
    h_gemm_k<EPI_BIAS_RES, false><<<dim3(D_RES / 128, NTOK / 128), 256, SMEM_DENSE>>>(
        p_post, DMLP, p_Wouth, D_RES, out, D_RES, DMLP, bout, p_mid, D_RES);
}